// round 10
// baseline (speedup 1.0000x reference)
#include <cuda_runtime.h>
#include <cuda_bf16.h>
#include <cstdint>

#define NN 100000
#define NNP 100096   // padded to CTA-tile multiple (pad rows never stored)
#define NE 1600000
#define NG 50
#define FD 128

// Scratch (allocation-free rule: __device__ globals)
__device__ float g_gp[NG * FD];
// A matrices pre-split to bf16 hi/lo, [NNP][128], k-contiguous
__device__ __nv_bfloat16 g_Nhi[(size_t)NNP * FD], g_Nlo[(size_t)NNP * FD];
__device__ __nv_bfloat16 g_Ihi[(size_t)NNP * FD], g_Ilo[(size_t)NNP * FD];
__device__ __nv_bfloat16 g_Ohi[(size_t)NNP * FD], g_Olo[(size_t)NNP * FD];
// B pre-split, layout [n=128][k=384] (k: Wn|Wi|Wo)
__device__ __nv_bfloat16 g_Bhi[FD * 3 * FD];
__device__ __nv_bfloat16 g_Blo[FD * 3 * FD];
// CSR binning scratch
__device__ int g_cnt_in[NN],  g_cnt_out[NN];
__device__ int g_off_in[NN],  g_off_out[NN];
__device__ int g_cur_in[NN],  g_cur_out[NN];
__device__ int g_bin_in[NE],  g_bin_out[NE];

// ---------------------------------------------------------------------------
__device__ __forceinline__ uint32_t smem_u32(const void* p) {
    uint32_t a;
    asm("{ .reg .u64 t; cvta.to.shared.u64 t, %1; cvt.u32.u64 %0, t; }"
        : "=r"(a) : "l"(p));
    return a;
}
__device__ __forceinline__ uint32_t pack_bf16(float x, float y) {
    __nv_bfloat162 t = __floats2bfloat162_rn(x, y);
    return *(uint32_t*)&t;
}
__device__ __forceinline__ float bf16_round(float x) {
    return __bfloat162float(__float2bfloat16_rn(x));
}

// ---------------------------------------------------------------------------
// CSR build: zero counts -> histogram -> exclusive scan -> fill bins
// ---------------------------------------------------------------------------
__global__ void init_counts_kernel() {
    int i = blockIdx.x * blockDim.x + threadIdx.x;
    if (i < NN) { g_cnt_in[i] = 0; g_cnt_out[i] = 0; }
}

__global__ void hist_kernel(const int* __restrict__ recv,
                            const int* __restrict__ send) {
    int t = blockIdx.x * blockDim.x + threadIdx.x;   // NE/4 threads
    if (t * 4 >= NE) return;
    int4 r = *(const int4*)(recv + t * 4);
    int4 s = *(const int4*)(send + t * 4);
    atomicAdd(&g_cnt_in[r.x], 1);  atomicAdd(&g_cnt_in[r.y], 1);
    atomicAdd(&g_cnt_in[r.z], 1);  atomicAdd(&g_cnt_in[r.w], 1);
    atomicAdd(&g_cnt_out[s.x], 1); atomicAdd(&g_cnt_out[s.y], 1);
    atomicAdd(&g_cnt_out[s.z], 1); atomicAdd(&g_cnt_out[s.w], 1);
}

#define SCAN_C 98
__global__ void scan_kernel() {
    const int* cnt = blockIdx.x ? g_cnt_out : g_cnt_in;
    int* off = blockIdx.x ? g_off_out : g_off_in;
    int* cur = blockIdx.x ? g_cur_out : g_cur_in;
    const int tid = threadIdx.x;
    const int base = tid * SCAN_C;
    int s = 0;
    for (int i = 0; i < SCAN_C; i++) {
        int idx = base + i;
        if (idx < NN) s += cnt[idx];
    }
    __shared__ int sh[1024];
    sh[tid] = s;
    __syncthreads();
    for (int o = 1; o < 1024; o <<= 1) {
        int v = (tid >= o) ? sh[tid - o] : 0;
        __syncthreads();
        sh[tid] += v;
        __syncthreads();
    }
    int run = sh[tid] - s;
    for (int i = 0; i < SCAN_C; i++) {
        int idx = base + i;
        if (idx < NN) {
            off[idx] = run;
            cur[idx] = run;
            run += cnt[idx];
        }
    }
}

__global__ void fill_kernel(const int* __restrict__ recv,
                            const int* __restrict__ send) {
    int t = blockIdx.x * blockDim.x + threadIdx.x;
    if (t * 4 >= NE) return;
    int e = t * 4;
    int4 r = *(const int4*)(recv + e);
    int4 s = *(const int4*)(send + e);
    g_bin_in[atomicAdd(&g_cur_in[r.x], 1)] = e;
    g_bin_in[atomicAdd(&g_cur_in[r.y], 1)] = e + 1;
    g_bin_in[atomicAdd(&g_cur_in[r.z], 1)] = e + 2;
    g_bin_in[atomicAdd(&g_cur_in[r.w], 1)] = e + 3;
    g_bin_out[atomicAdd(&g_cur_out[s.x], 1)] = e;
    g_bin_out[atomicAdd(&g_cur_out[s.y], 1)] = e + 1;
    g_bin_out[atomicAdd(&g_cur_out[s.z], 1)] = e + 2;
    g_bin_out[atomicAdd(&g_cur_out[s.w], 1)] = e + 3;
}

// ---------------------------------------------------------------------------
// Gather: warp per node per direction; writes bf16 hi/lo split DIRECTLY.
// ---------------------------------------------------------------------------
__global__ void __launch_bounds__(256)
gather_kernel(const float* __restrict__ ef) {
    const int warp = threadIdx.x >> 5;
    const int lane = threadIdx.x & 31;
    const int node = blockIdx.x * 8 + warp;
    if (node >= NN) return;
    const int* off; const int* cnt; const int* bin;
    __nv_bfloat16* ahi; __nv_bfloat16* alo;
    if (blockIdx.y == 0) { off = g_off_in;  cnt = g_cnt_in;  bin = g_bin_in;
                           ahi = g_Ihi; alo = g_Ilo; }
    else                 { off = g_off_out; cnt = g_cnt_out; bin = g_bin_out;
                           ahi = g_Ohi; alo = g_Olo; }

    const int start = __ldg(off + node);
    const int end   = start + __ldg(cnt + node);
    const float4* ef4 = (const float4*)ef;
    float4 acc = make_float4(0.f, 0.f, 0.f, 0.f);

    int j = start;
    for (; j + 4 <= end; j += 4) {
        int i0 = __ldg(bin + j), i1 = __ldg(bin + j + 1);
        int i2 = __ldg(bin + j + 2), i3 = __ldg(bin + j + 3);
        float4 v0 = __ldg(ef4 + (size_t)i0 * 32 + lane);
        float4 v1 = __ldg(ef4 + (size_t)i1 * 32 + lane);
        float4 v2 = __ldg(ef4 + (size_t)i2 * 32 + lane);
        float4 v3 = __ldg(ef4 + (size_t)i3 * 32 + lane);
        acc.x += (v0.x + v1.x) + (v2.x + v3.x);
        acc.y += (v0.y + v1.y) + (v2.y + v3.y);
        acc.z += (v0.z + v1.z) + (v2.z + v3.z);
        acc.w += (v0.w + v1.w) + (v2.w + v3.w);
    }
    for (; j < end; j++) {
        int i0 = __ldg(bin + j);
        float4 v = __ldg(ef4 + (size_t)i0 * 32 + lane);
        acc.x += v.x; acc.y += v.y; acc.z += v.z; acc.w += v.w;
    }
    float h0 = bf16_round(acc.x), h1 = bf16_round(acc.y);
    float h2 = bf16_round(acc.z), h3 = bf16_round(acc.w);
    uint2 hv = make_uint2(pack_bf16(h0, h1), pack_bf16(h2, h3));
    uint2 lv = make_uint2(pack_bf16(acc.x - h0, acc.y - h1),
                          pack_bf16(acc.z - h2, acc.w - h3));
    *(uint2*)(ahi + (size_t)node * FD + lane * 4) = hv;
    *(uint2*)(alo + (size_t)node * FD + lane * 4) = lv;
}

// ---------------------------------------------------------------------------
// node_features fp32 -> bf16 hi/lo
// ---------------------------------------------------------------------------
__global__ void node_split_kernel(const float* __restrict__ node) {
    size_t t = (size_t)blockIdx.x * blockDim.x + threadIdx.x;
    if (t * 4 >= (size_t)NN * FD) return;
    float4 v = *(const float4*)(node + t * 4);
    float h0 = bf16_round(v.x), h1 = bf16_round(v.y);
    float h2 = bf16_round(v.z), h3 = bf16_round(v.w);
    *(uint2*)(g_Nhi + t * 4) = make_uint2(pack_bf16(h0, h1), pack_bf16(h2, h3));
    *(uint2*)(g_Nlo + t * 4) = make_uint2(pack_bf16(v.x - h0, v.y - h1),
                                          pack_bf16(v.z - h2, v.w - h3));
}

// ---------------------------------------------------------------------------
// gp[g][n] = bias[n] + glob[g] . Wg[n]   — warp per output, shfl reduce
// ---------------------------------------------------------------------------
__global__ void __launch_bounds__(256)
globproj_kernel(const float* __restrict__ gf,
                const float* __restrict__ Wg,
                const float* __restrict__ bias) {
    const int warp = threadIdx.x >> 5;
    const int lane = threadIdx.x & 31;
    const int idx = blockIdx.x * 8 + warp;
    if (idx >= NG * FD) return;
    const int g = idx >> 7, n = idx & 127;
    const float* gr = gf + (size_t)g * FD;
    const float* wr = Wg + (size_t)n * FD;
    float s = 0.f;
    #pragma unroll
    for (int q = 0; q < 4; q++)
        s += __ldg(gr + lane + q * 32) * __ldg(wr + lane + q * 32);
    #pragma unroll
    for (int o = 16; o > 0; o >>= 1) s += __shfl_xor_sync(0xFFFFFFFFu, s, o);
    if (lane == 0) g_gp[idx] = s + __ldg(bias + n);
}

// ---------------------------------------------------------------------------
// B split [n][384] bf16 hi/lo
// ---------------------------------------------------------------------------
__global__ void b_split_kernel(const float* __restrict__ Wn,
                               const float* __restrict__ Wi,
                               const float* __restrict__ Wo) {
    int idx = blockIdx.x * blockDim.x + threadIdx.x;
    if (idx >= FD * 3 * FD) return;
    int n = idx / (3 * FD);
    int k = idx % (3 * FD);
    int seg = k >> 7, kk = k & 127;
    const float* W = (seg == 0) ? Wn : (seg == 1) ? Wi : Wo;
    float x = W[n * FD + kk];
    float hf = bf16_round(x);
    g_Bhi[idx] = __float2bfloat16_rn(hf);
    g_Blo[idx] = __float2bfloat16_rn(x - hf);
}

// ---------------------------------------------------------------------------
// GEMM: mma.sync m16n8k16 bf16, 3-term split, 2-stage cp.async pipeline,
// ldmatrix.x4 fragment loads. CTA 128x128, 8 warps 4(m)x2(n).
// ---------------------------------------------------------------------------
#define KP 40
#define TILE_BYTES (128 * KP * 2)        // 10240
#define STAGE_BYTES (4 * TILE_BYTES)     // 40960
#define AHI_OFF(s) ((s) * STAGE_BYTES)
#define ALO_OFF(s) ((s) * STAGE_BYTES + TILE_BYTES)
#define BHI_OFF(s) ((s) * STAGE_BYTES + 2 * TILE_BYTES)
#define BLO_OFF(s) ((s) * STAGE_BYTES + 3 * TILE_BYTES)
#define GEMM_SMEM (2 * STAGE_BYTES)      // 81920 -> 2 CTAs/SM

#define MMA_BF16(acc, a0, a1, a2, a3, b0, b1)                               \
    asm volatile(                                                           \
        "mma.sync.aligned.m16n8k16.row.col.f32.bf16.bf16.f32 "              \
        "{%0,%1,%2,%3}, {%4,%5,%6,%7}, {%8,%9}, {%0,%1,%2,%3};"             \
        : "+f"(acc[0]), "+f"(acc[1]), "+f"(acc[2]), "+f"(acc[3])            \
        : "r"(a0), "r"(a1), "r"(a2), "r"(a3), "r"(b0), "r"(b1))

#define LDX4(r, addr)                                                       \
    asm volatile("ldmatrix.sync.aligned.m8n8.x4.shared.b16 "                \
                 "{%0,%1,%2,%3}, [%4];"                                     \
                 : "=r"((r)[0]), "=r"((r)[1]), "=r"((r)[2]), "=r"((r)[3])   \
                 : "r"(addr))

__global__ void __launch_bounds__(256, 2)
gemm_mma_kernel(const int* __restrict__ gidx, float* __restrict__ out) {
    extern __shared__ __align__(128) char smem[];
    const uint32_t sb = smem_u32(smem);
    const int tid    = threadIdx.x;
    const int wid    = tid >> 5;
    const int lane   = tid & 31;
    const int gid    = lane >> 2;
    const int t2     = (lane & 3) * 2;
    const int warp_m = (wid & 3) * 32;
    const int warp_n = (wid >> 2) * 64;
    const int m0     = blockIdx.x * 128;

    // ldmatrix per-lane fragment addressing: row = base + (lane&15),
    // k-half = (lane>>4)*8
    const int frow = lane & 15;
    const int fk   = (lane >> 4) * 8;
    uint32_t a_off[2], b_off[4];
    #pragma unroll
    for (int ma = 0; ma < 2; ma++)
        a_off[ma] = ((warp_m + ma * 16 + frow) * KP + fk) * 2;
    #pragma unroll
    for (int np = 0; np < 4; np++)
        b_off[np] = ((warp_n + np * 16 + frow) * KP + fk) * 2;

    float acc[16][4];
    #pragma unroll
    for (int i = 0; i < 16; i++)
        #pragma unroll
        for (int j = 0; j < 4; j++) acc[i][j] = 0.f;

    // chunk loader: 8 cp.asyncs per thread (A hi/lo + B hi/lo, 16B granules)
    auto load_chunk = [&](int kb, int s) {
        const int seg   = kb >> 2;
        const int kloc  = (kb & 3) * 32;
        const int kglob = seg * FD + kloc;
        const __nv_bfloat16* Ah = (seg == 0) ? g_Nhi : (seg == 1) ? g_Ihi : g_Ohi;
        const __nv_bfloat16* Al = (seg == 0) ? g_Nlo : (seg == 1) ? g_Ilo : g_Olo;
        #pragma unroll
        for (int i = 0; i < 2; i++) {
            int c = tid * 2 + i;            // 0..511
            int row = c >> 2, sub = c & 3;  // 16B granule
            uint32_t doff = (uint32_t)(row * (KP * 2) + sub * 16);
            const __nv_bfloat16* sa_hi = Ah + (size_t)(m0 + row) * FD + kloc + sub * 8;
            const __nv_bfloat16* sa_lo = Al + (size_t)(m0 + row) * FD + kloc + sub * 8;
            const __nv_bfloat16* sb_hi = g_Bhi + (size_t)row * (3 * FD) + kglob + sub * 8;
            const __nv_bfloat16* sb_lo = g_Blo + (size_t)row * (3 * FD) + kglob + sub * 8;
            asm volatile("cp.async.cg.shared.global [%0], [%1], 16;"
                         :: "r"(sb + AHI_OFF(s) + doff), "l"(sa_hi) : "memory");
            asm volatile("cp.async.cg.shared.global [%0], [%1], 16;"
                         :: "r"(sb + ALO_OFF(s) + doff), "l"(sa_lo) : "memory");
            asm volatile("cp.async.cg.shared.global [%0], [%1], 16;"
                         :: "r"(sb + BHI_OFF(s) + doff), "l"(sb_hi) : "memory");
            asm volatile("cp.async.cg.shared.global [%0], [%1], 16;"
                         :: "r"(sb + BLO_OFF(s) + doff), "l"(sb_lo) : "memory");
        }
        asm volatile("cp.async.commit_group;" ::: "memory");
    };

    load_chunk(0, 0);

    #pragma unroll 1
    for (int kb = 0; kb < 12; kb++) {
        const int s = kb & 1;
        if (kb < 11) {
            load_chunk(kb + 1, s ^ 1);
            asm volatile("cp.async.wait_group 1;" ::: "memory");
        } else {
            asm volatile("cp.async.wait_group 0;" ::: "memory");
        }
        __syncthreads();

        #pragma unroll
        for (int ks = 0; ks < 2; ks++) {
            const uint32_t kbyte = ks * 32;
            uint32_t ahi[2][4], alo[2][4];
            #pragma unroll
            for (int ma = 0; ma < 2; ma++) {
                LDX4(ahi[ma], sb + AHI_OFF(s) + a_off[ma] + kbyte);
                LDX4(alo[ma], sb + ALO_OFF(s) + a_off[ma] + kbyte);
            }
            #pragma unroll
            for (int np = 0; np < 4; np++) {
                uint32_t bh[4], bl[4];
                LDX4(bh, sb + BHI_OFF(s) + b_off[np] + kbyte);
                LDX4(bl, sb + BLO_OFF(s) + b_off[np] + kbyte);
                #pragma unroll
                for (int ma = 0; ma < 2; ma++) {
                    float* a0 = acc[ma * 8 + np * 2];
                    float* a1 = acc[ma * 8 + np * 2 + 1];
                    MMA_BF16(a0, ahi[ma][0], ahi[ma][1], ahi[ma][2], ahi[ma][3], bh[0], bh[2]);
                    MMA_BF16(a0, ahi[ma][0], ahi[ma][1], ahi[ma][2], ahi[ma][3], bl[0], bl[2]);
                    MMA_BF16(a0, alo[ma][0], alo[ma][1], alo[ma][2], alo[ma][3], bh[0], bh[2]);
                    MMA_BF16(a1, ahi[ma][0], ahi[ma][1], ahi[ma][2], ahi[ma][3], bh[1], bh[3]);
                    MMA_BF16(a1, ahi[ma][0], ahi[ma][1], ahi[ma][2], ahi[ma][3], bl[1], bl[3]);
                    MMA_BF16(a1, alo[ma][0], alo[ma][1], alo[ma][2], alo[ma][3], bh[1], bh[3]);
                }
            }
        }
        __syncthreads();
    }

    // ---- epilogue: + gp[graph_idx[m]] (bias folded), store ----
    #pragma unroll
    for (int ma = 0; ma < 2; ma++) {
        const int mr0 = m0 + warp_m + ma * 16 + gid;
        const int mr1 = mr0 + 8;
        const int g0 = (mr0 < NN) ? __ldg(gidx + mr0) : 0;
        const int g1 = (mr1 < NN) ? __ldg(gidx + mr1) : 0;
        #pragma unroll
        for (int na = 0; na < 8; na++) {
            const int n = warp_n + na * 8 + t2;
            const float* a = acc[ma * 8 + na];
            if (mr0 < NN) {
                float2 b = *(const float2*)(g_gp + (size_t)g0 * FD + n);
                *(float2*)(out + (size_t)mr0 * FD + n) =
                    make_float2(a[0] + b.x, a[1] + b.y);
            }
            if (mr1 < NN) {
                float2 b = *(const float2*)(g_gp + (size_t)g1 * FD + n);
                *(float2*)(out + (size_t)mr1 * FD + n) =
                    make_float2(a[2] + b.x, a[3] + b.y);
            }
        }
    }
}

// ---------------------------------------------------------------------------
extern "C" void kernel_launch(void* const* d_in, const int* in_sizes, int n_in,
                              void* d_out, int out_size) {
    const float* node = (const float*)d_in[0];
    const float* edge = (const float*)d_in[1];
    const float* glob = (const float*)d_in[2];
    const float* Wn   = (const float*)d_in[3];
    const float* Wi   = (const float*)d_in[4];
    const float* Wo   = (const float*)d_in[5];
    const float* Wg   = (const float*)d_in[6];
    const float* bias = (const float*)d_in[7];
    const int* recv   = (const int*)d_in[8];
    const int* send   = (const int*)d_in[9];
    const int* gidx   = (const int*)d_in[10];
    float* out        = (float*)d_out;

    cudaFuncSetAttribute(gemm_mma_kernel,
                         cudaFuncAttributeMaxDynamicSharedMemorySize, GEMM_SMEM);

    // CSR build
    init_counts_kernel<<<(NN + 255) / 256, 256>>>();
    hist_kernel<<<(NE / 4 + 255) / 256, 256>>>(recv, send);
    scan_kernel<<<2, 1024>>>();
    fill_kernel<<<(NE / 4 + 255) / 256, 256>>>(recv, send);
    // aggregate + convert to bf16 hi/lo in one pass
    dim3 ggrid((NN + 7) / 8, 2);
    gather_kernel<<<ggrid, 256>>>(edge);
    // conversions / small preps
    node_split_kernel<<<(int)(((size_t)NN * FD / 4 + 255) / 256), 256>>>(node);
    b_split_kernel<<<(FD * 3 * FD + 255) / 256, 256>>>(Wn, Wi, Wo);
    globproj_kernel<<<(NG * FD + 7) / 8, 256>>>(glob, Wg, bias);
    // fused projection GEMM (pipelined, tensor-core)
    gemm_mma_kernel<<<(NNP + 127) / 128, 256, GEMM_SMEM>>>(gidx, out);
}

// round 13
// speedup vs baseline: 1.3368x; 1.3368x over previous
#include <cuda_runtime.h>
#include <cuda_bf16.h>
#include <cstdint>

#define NN 100000
#define NE 1600000
#define NG 50
#define FD 128

// Scratch (allocation-free rule: __device__ globals)
__device__ float g_agg_in[(size_t)NN * FD];
__device__ float g_agg_out[(size_t)NN * FD];
__device__ float g_gp[NG * FD];
__device__ __nv_bfloat16 g_Bhi[FD * 3 * FD];
__device__ __nv_bfloat16 g_Blo[FD * 3 * FD];
// CSR binning scratch
__device__ int g_cnt_in[NN],  g_cnt_out[NN];
__device__ int g_off_in[NN],  g_off_out[NN];
__device__ int g_cur_in[NN],  g_cur_out[NN];
__device__ int g_bin_in[NE],  g_bin_out[NE];

// ---------------------------------------------------------------------------
__device__ __forceinline__ uint32_t smem_u32(const void* p) {
    uint32_t a;
    asm("{ .reg .u64 t; cvta.to.shared.u64 t, %1; cvt.u32.u64 %0, t; }"
        : "=r"(a) : "l"(p));
    return a;
}
__device__ __forceinline__ uint32_t pack_bf16(float x, float y) {
    __nv_bfloat162 t = __floats2bfloat162_rn(x, y);
    return *(uint32_t*)&t;
}
__device__ __forceinline__ float bf16_round(float x) {
    return __bfloat162float(__float2bfloat16_rn(x));
}

// ---------------------------------------------------------------------------
// CSR build (verbatim R9)
// ---------------------------------------------------------------------------
__global__ void init_counts_kernel() {
    int i = blockIdx.x * blockDim.x + threadIdx.x;
    if (i < NN) { g_cnt_in[i] = 0; g_cnt_out[i] = 0; }
}

__global__ void hist_kernel(const int* __restrict__ recv,
                            const int* __restrict__ send) {
    int e = blockIdx.x * blockDim.x + threadIdx.x;
    if (e < NE) {
        atomicAdd(&g_cnt_in[recv[e]], 1);
        atomicAdd(&g_cnt_out[send[e]], 1);
    }
}

#define SCAN_C 98
__global__ void scan_kernel() {
    const int* cnt = blockIdx.x ? g_cnt_out : g_cnt_in;
    int* off = blockIdx.x ? g_off_out : g_off_in;
    int* cur = blockIdx.x ? g_cur_out : g_cur_in;
    const int tid = threadIdx.x;
    const int base = tid * SCAN_C;
    int s = 0;
    for (int i = 0; i < SCAN_C; i++) {
        int idx = base + i;
        if (idx < NN) s += cnt[idx];
    }
    __shared__ int sh[1024];
    sh[tid] = s;
    __syncthreads();
    for (int o = 1; o < 1024; o <<= 1) {
        int v = (tid >= o) ? sh[tid - o] : 0;
        __syncthreads();
        sh[tid] += v;
        __syncthreads();
    }
    int run = sh[tid] - s;
    for (int i = 0; i < SCAN_C; i++) {
        int idx = base + i;
        if (idx < NN) {
            off[idx] = run;
            cur[idx] = run;
            run += cnt[idx];
        }
    }
}

__global__ void fill_kernel(const int* __restrict__ recv,
                            const int* __restrict__ send) {
    int e = blockIdx.x * blockDim.x + threadIdx.x;
    if (e < NE) {
        int p = atomicAdd(&g_cur_in[recv[e]], 1);
        g_bin_in[p] = e;
        int q = atomicAdd(&g_cur_out[send[e]], 1);
        g_bin_out[q] = e;
    }
}

// ---------------------------------------------------------------------------
// Gather (verbatim R9): warp per node per direction, fp32 agg write
// ---------------------------------------------------------------------------
__global__ void __launch_bounds__(256)
gather_kernel(const float* __restrict__ ef) {
    const int warp = threadIdx.x >> 5;
    const int lane = threadIdx.x & 31;
    const int node = blockIdx.x * 8 + warp;
    if (node >= NN) return;
    const int* off; const int* cnt; const int* bin; float* agg;
    if (blockIdx.y == 0) { off = g_off_in;  cnt = g_cnt_in;  bin = g_bin_in;  agg = g_agg_in; }
    else                 { off = g_off_out; cnt = g_cnt_out; bin = g_bin_out; agg = g_agg_out; }

    const int start = __ldg(off + node);
    const int end   = start + __ldg(cnt + node);
    const float4* ef4 = (const float4*)ef;
    float4 acc = make_float4(0.f, 0.f, 0.f, 0.f);

    int j = start;
    for (; j + 4 <= end; j += 4) {
        int i0 = __ldg(bin + j), i1 = __ldg(bin + j + 1);
        int i2 = __ldg(bin + j + 2), i3 = __ldg(bin + j + 3);
        float4 v0 = __ldg(ef4 + (size_t)i0 * 32 + lane);
        float4 v1 = __ldg(ef4 + (size_t)i1 * 32 + lane);
        float4 v2 = __ldg(ef4 + (size_t)i2 * 32 + lane);
        float4 v3 = __ldg(ef4 + (size_t)i3 * 32 + lane);
        acc.x += (v0.x + v1.x) + (v2.x + v3.x);
        acc.y += (v0.y + v1.y) + (v2.y + v3.y);
        acc.z += (v0.z + v1.z) + (v2.z + v3.z);
        acc.w += (v0.w + v1.w) + (v2.w + v3.w);
    }
    for (; j < end; j++) {
        int i0 = __ldg(bin + j);
        float4 v = __ldg(ef4 + (size_t)i0 * 32 + lane);
        acc.x += v.x; acc.y += v.y; acc.z += v.z; acc.w += v.w;
    }
    ((float4*)(agg + (size_t)node * FD))[lane] = acc;
}

// ---------------------------------------------------------------------------
// globproj (verbatim R9)
// ---------------------------------------------------------------------------
__global__ void __launch_bounds__(256)
globproj_kernel(const float* __restrict__ gf,
                const float* __restrict__ Wg,
                const float* __restrict__ bias) {
    const int warp = threadIdx.x >> 5;
    const int lane = threadIdx.x & 31;
    const int idx = blockIdx.x * 8 + warp;
    if (idx >= NG * FD) return;
    const int g = idx >> 7, n = idx & 127;
    const float* gr = gf + (size_t)g * FD;
    const float* wr = Wg + (size_t)n * FD;
    float s = 0.f;
    #pragma unroll
    for (int q = 0; q < 4; q++)
        s += __ldg(gr + lane + q * 32) * __ldg(wr + lane + q * 32);
    #pragma unroll
    for (int o = 16; o > 0; o >>= 1) s += __shfl_xor_sync(0xFFFFFFFFu, s, o);
    if (lane == 0) g_gp[idx] = s + __ldg(bias + n);
}

// ---------------------------------------------------------------------------
// B split (verbatim R9)
// ---------------------------------------------------------------------------
__global__ void b_split_kernel(const float* __restrict__ Wn,
                               const float* __restrict__ Wi,
                               const float* __restrict__ Wo) {
    int idx = blockIdx.x * blockDim.x + threadIdx.x;
    if (idx >= FD * 3 * FD) return;
    int n = idx / (3 * FD);
    int k = idx % (3 * FD);
    int seg = k >> 7, kk = k & 127;
    const float* W = (seg == 0) ? Wn : (seg == 1) ? Wi : Wo;
    float x = W[n * FD + kk];
    float hf = bf16_round(x);
    g_Bhi[idx] = __float2bfloat16_rn(hf);
    g_Blo[idx] = __float2bfloat16_rn(x - hf);
}

// ---------------------------------------------------------------------------
// GEMM (R9 layout/fragments, software-pipelined):
// while computing chunk kb from stage s, chunk kb+1's A rows are in flight
// in registers and its B cp.asyncs stream into stage s^1; convert+STS after
// the MMAs. Double-buffered dynamic SMEM (80KB), 2 CTAs/SM.
// ---------------------------------------------------------------------------
#define KP 40
#define TILE_BYTES (128 * KP * 2)        // 10240
#define STAGE_BYTES (4 * TILE_BYTES)     // 40960
#define AHI_OFF(s) ((s) * STAGE_BYTES)
#define ALO_OFF(s) ((s) * STAGE_BYTES + TILE_BYTES)
#define BHI_OFF(s) ((s) * STAGE_BYTES + 2 * TILE_BYTES)
#define BLO_OFF(s) ((s) * STAGE_BYTES + 3 * TILE_BYTES)
#define GEMM_SMEM (2 * STAGE_BYTES)      // 81920

#define MMA_BF16(acc, a0, a1, a2, a3, b0, b1)                               \
    asm volatile(                                                           \
        "mma.sync.aligned.m16n8k16.row.col.f32.bf16.bf16.f32 "              \
        "{%0,%1,%2,%3}, {%4,%5,%6,%7}, {%8,%9}, {%0,%1,%2,%3};"             \
        : "+f"(acc[0]), "+f"(acc[1]), "+f"(acc[2]), "+f"(acc[3])            \
        : "r"(a0), "r"(a1), "r"(a2), "r"(a3), "r"(b0), "r"(b1))

__global__ void __launch_bounds__(256, 2)
gemm_mma_kernel(const float* __restrict__ node,
                const int* __restrict__ gidx,
                float* __restrict__ out) {
    extern __shared__ __align__(16) char smem[];
    const uint32_t sb = smem_u32(smem);
    __nv_bfloat16* const smb = (__nv_bfloat16*)smem;

    const int tid    = threadIdx.x;
    const int wid    = tid >> 5;
    const int lane   = tid & 31;
    const int gid    = lane >> 2;
    const int t2     = (lane & 3) * 2;
    const int warp_m = (wid & 3) * 32;
    const int warp_n = (wid >> 2) * 64;
    const int m0     = blockIdx.x * 128;

    const int arow  = tid >> 1;
    const int ahalf = tid & 1;
    const int gm    = m0 + arow;

    float acc[16][4];
    #pragma unroll
    for (int i = 0; i < 16; i++)
        #pragma unroll
        for (int j = 0; j < 4; j++) acc[i][j] = 0.f;

    // B loader: 4 cp.asyncs per thread into stage st
    auto load_B = [&](int kb, int st) {
        const int kglob = (kb >> 2) * FD + (kb & 3) * 32;
        #pragma unroll
        for (int i = 0; i < 2; i++) {
            int c = tid * 2 + i;
            int row = c >> 2, sub = c & 3;
            uint32_t doff = (uint32_t)(row * (KP * 2) + sub * 16);
            const __nv_bfloat16* sh = g_Bhi + (size_t)row * (3 * FD) + kglob + sub * 8;
            const __nv_bfloat16* sl = g_Blo + (size_t)row * (3 * FD) + kglob + sub * 8;
            asm volatile("cp.async.cg.shared.global [%0], [%1], 16;"
                         :: "r"(sb + BHI_OFF(st) + doff), "l"(sh) : "memory");
            asm volatile("cp.async.cg.shared.global [%0], [%1], 16;"
                         :: "r"(sb + BLO_OFF(st) + doff), "l"(sl) : "memory");
        }
        asm volatile("cp.async.commit_group;" ::: "memory");
    };
    // A LDG into regs
    auto load_A = [&](int kb, float4* v) {
        const int seg  = kb >> 2;
        const int kloc = (kb & 3) * 32;
        const float* X = (seg == 0) ? node : (seg == 1) ? g_agg_in : g_agg_out;
        #pragma unroll
        for (int j = 0; j < 4; j++) {
            if (gm < NN)
                v[j] = *(const float4*)(X + (size_t)gm * FD + kloc + ahalf * 16 + j * 4);
            else
                v[j] = make_float4(0.f, 0.f, 0.f, 0.f);
        }
    };
    // convert + STS A into stage st
    auto store_A = [&](const float4* v, int st) {
        uint32_t hw[8], lw[8];
        #pragma unroll
        for (int j = 0; j < 4; j++) {
            float f[4] = {v[j].x, v[j].y, v[j].z, v[j].w};
            float hf[4];
            #pragma unroll
            for (int q = 0; q < 4; q++) hf[q] = bf16_round(f[q]);
            hw[j * 2 + 0] = pack_bf16(hf[0], hf[1]);
            hw[j * 2 + 1] = pack_bf16(hf[2], hf[3]);
            lw[j * 2 + 0] = pack_bf16(f[0] - hf[0], f[1] - hf[1]);
            lw[j * 2 + 1] = pack_bf16(f[2] - hf[2], f[3] - hf[3]);
        }
        __nv_bfloat16* ah = smb + (AHI_OFF(st) >> 1) + arow * KP + ahalf * 16;
        __nv_bfloat16* al = smb + (ALO_OFF(st) >> 1) + arow * KP + ahalf * 16;
        *(uint4*)(ah)     = make_uint4(hw[0], hw[1], hw[2], hw[3]);
        *(uint4*)(ah + 8) = make_uint4(hw[4], hw[5], hw[6], hw[7]);
        *(uint4*)(al)     = make_uint4(lw[0], lw[1], lw[2], lw[3]);
        *(uint4*)(al + 8) = make_uint4(lw[4], lw[5], lw[6], lw[7]);
    };

    // ---- prologue: stage chunk 0 into stage 0 ----
    {
        float4 v[4];
        load_B(0, 0);
        load_A(0, v);
        store_A(v, 0);
        asm volatile("cp.async.wait_group 0;" ::: "memory");
        __syncthreads();
    }

    #pragma unroll 1
    for (int kb = 0; kb < 12; kb++) {
        const int s = kb & 1;
        float4 v[4];
        const bool have_next = (kb < 11);
        if (have_next) {
            load_A(kb + 1, v);         // LDG early (in flight during MMAs)
            load_B(kb + 1, s ^ 1);     // cp.async into other stage
        }

        // ---- compute chunk kb from stage s (verbatim R9 fragments) ----
        const __nv_bfloat16* Ash = smb + (AHI_OFF(s) >> 1);
        const __nv_bfloat16* Asl = smb + (ALO_OFF(s) >> 1);
        const __nv_bfloat16* Bsh = smb + (BHI_OFF(s) >> 1);
        const __nv_bfloat16* Bsl = smb + (BLO_OFF(s) >> 1);
        #pragma unroll
        for (int ks = 0; ks < 2; ks++) {
            const int kofs = ks * 16 + t2;
            uint32_t ahi[2][4], alo[2][4];
            #pragma unroll
            for (int ma = 0; ma < 2; ma++) {
                const int r = warp_m + ma * 16 + gid;
                ahi[ma][0] = *(const uint32_t*)&Ash[r * KP + kofs];
                ahi[ma][1] = *(const uint32_t*)&Ash[(r + 8) * KP + kofs];
                ahi[ma][2] = *(const uint32_t*)&Ash[r * KP + kofs + 8];
                ahi[ma][3] = *(const uint32_t*)&Ash[(r + 8) * KP + kofs + 8];
                alo[ma][0] = *(const uint32_t*)&Asl[r * KP + kofs];
                alo[ma][1] = *(const uint32_t*)&Asl[(r + 8) * KP + kofs];
                alo[ma][2] = *(const uint32_t*)&Asl[r * KP + kofs + 8];
                alo[ma][3] = *(const uint32_t*)&Asl[(r + 8) * KP + kofs + 8];
            }
            #pragma unroll
            for (int na = 0; na < 8; na++) {
                const int bn = warp_n + na * 8 + gid;
                uint32_t bhi0 = *(const uint32_t*)&Bsh[bn * KP + kofs];
                uint32_t bhi1 = *(const uint32_t*)&Bsh[bn * KP + kofs + 8];
                uint32_t blo0 = *(const uint32_t*)&Bsl[bn * KP + kofs];
                uint32_t blo1 = *(const uint32_t*)&Bsl[bn * KP + kofs + 8];
                #pragma unroll
                for (int ma = 0; ma < 2; ma++) {
                    float* a = acc[ma * 8 + na];
                    MMA_BF16(a, ahi[ma][0], ahi[ma][1], ahi[ma][2], ahi[ma][3], bhi0, bhi1);
                    MMA_BF16(a, ahi[ma][0], ahi[ma][1], ahi[ma][2], ahi[ma][3], blo0, blo1);
                    MMA_BF16(a, alo[ma][0], alo[ma][1], alo[ma][2], alo[ma][3], bhi0, bhi1);
                }
            }
        }

        if (have_next) {
            store_A(v, s ^ 1);                               // STS late
            asm volatile("cp.async.wait_group 0;" ::: "memory");
        }
        __syncthreads();
    }

    // ---- epilogue (verbatim R9) ----
    #pragma unroll
    for (int ma = 0; ma < 2; ma++) {
        const int mr0 = m0 + warp_m + ma * 16 + gid;
        const int mr1 = mr0 + 8;
        const int g0 = (mr0 < NN) ? __ldg(gidx + mr0) : 0;
        const int g1 = (mr1 < NN) ? __ldg(gidx + mr1) : 0;
        #pragma unroll
        for (int na = 0; na < 8; na++) {
            const int n = warp_n + na * 8 + t2;
            const float* a = acc[ma * 8 + na];
            if (mr0 < NN) {
                float2 b = *(const float2*)(g_gp + (size_t)g0 * FD + n);
                *(float2*)(out + (size_t)mr0 * FD + n) =
                    make_float2(a[0] + b.x, a[1] + b.y);
            }
            if (mr1 < NN) {
                float2 b = *(const float2*)(g_gp + (size_t)g1 * FD + n);
                *(float2*)(out + (size_t)mr1 * FD + n) =
                    make_float2(a[2] + b.x, a[3] + b.y);
            }
        }
    }
}

// ---------------------------------------------------------------------------
extern "C" void kernel_launch(void* const* d_in, const int* in_sizes, int n_in,
                              void* d_out, int out_size) {
    const float* node = (const float*)d_in[0];
    const float* edge = (const float*)d_in[1];
    const float* glob = (const float*)d_in[2];
    const float* Wn   = (const float*)d_in[3];
    const float* Wi   = (const float*)d_in[4];
    const float* Wo   = (const float*)d_in[5];
    const float* Wg   = (const float*)d_in[6];
    const float* bias = (const float*)d_in[7];
    const int* recv   = (const int*)d_in[8];
    const int* send   = (const int*)d_in[9];
    const int* gidx   = (const int*)d_in[10];
    float* out        = (float*)d_out;

    cudaFuncSetAttribute(gemm_mma_kernel,
                         cudaFuncAttributeMaxDynamicSharedMemorySize, GEMM_SMEM);

    // CSR build (R9)
    init_counts_kernel<<<(NN + 255) / 256, 256>>>();
    hist_kernel<<<(NE + 255) / 256, 256>>>(recv, send);
    scan_kernel<<<2, 1024>>>();
    fill_kernel<<<(NE + 255) / 256, 256>>>(recv, send);
    // aggregate via gather (R9)
    dim3 ggrid((NN + 7) / 8, 2);
    gather_kernel<<<ggrid, 256>>>(edge);
    // small preps (R9)
    b_split_kernel<<<(FD * 3 * FD + 255) / 256, 256>>>(Wn, Wi, Wo);
    globproj_kernel<<<(NG * FD + 7) / 8, 256>>>(glob, Wg, bias);
    // fused projection GEMM — pipelined
    gemm_mma_kernel<<<(NN + 127) / 128, 256, GEMM_SMEM>>>(node, gidx, out);
}

// round 14
// speedup vs baseline: 1.4514x; 1.0857x over previous
#include <cuda_runtime.h>
#include <cuda_bf16.h>
#include <cuda_fp16.h>
#include <cstdint>

#define NN 100000
#define NE 1600000
#define NG 50
#define FD 128

// Scratch (allocation-free rule: __device__ globals)
__device__ float g_agg_in[(size_t)NN * FD];
__device__ float g_agg_out[(size_t)NN * FD];
__device__ float g_gp[NG * FD];
__device__ __half g_Bh[FD * 3 * FD];   // fp16 weights, layout [n=128][k=384]
// CSR binning scratch
__device__ int g_cnt_in[NN],  g_cnt_out[NN];
__device__ int g_off_in[NN],  g_off_out[NN];
__device__ int g_cur_in[NN],  g_cur_out[NN];
__device__ int g_bin_in[NE],  g_bin_out[NE];

// ---------------------------------------------------------------------------
__device__ __forceinline__ uint32_t smem_u32(const void* p) {
    uint32_t a;
    asm("{ .reg .u64 t; cvta.to.shared.u64 t, %1; cvt.u32.u64 %0, t; }"
        : "=r"(a) : "l"(p));
    return a;
}
__device__ __forceinline__ uint32_t pack_f16(float x, float y) {
    __half2 t = __floats2half2_rn(x, y);   // .x = low half
    return *(uint32_t*)&t;
}

// ---------------------------------------------------------------------------
// CSR build (verbatim R13)
// ---------------------------------------------------------------------------
__global__ void init_counts_kernel() {
    int i = blockIdx.x * blockDim.x + threadIdx.x;
    if (i < NN) { g_cnt_in[i] = 0; g_cnt_out[i] = 0; }
}

__global__ void hist_kernel(const int* __restrict__ recv,
                            const int* __restrict__ send) {
    int e = blockIdx.x * blockDim.x + threadIdx.x;
    if (e < NE) {
        atomicAdd(&g_cnt_in[recv[e]], 1);
        atomicAdd(&g_cnt_out[send[e]], 1);
    }
}

#define SCAN_C 98
__global__ void scan_kernel() {
    const int* cnt = blockIdx.x ? g_cnt_out : g_cnt_in;
    int* off = blockIdx.x ? g_off_out : g_off_in;
    int* cur = blockIdx.x ? g_cur_out : g_cur_in;
    const int tid = threadIdx.x;
    const int base = tid * SCAN_C;
    int s = 0;
    for (int i = 0; i < SCAN_C; i++) {
        int idx = base + i;
        if (idx < NN) s += cnt[idx];
    }
    __shared__ int sh[1024];
    sh[tid] = s;
    __syncthreads();
    for (int o = 1; o < 1024; o <<= 1) {
        int v = (tid >= o) ? sh[tid - o] : 0;
        __syncthreads();
        sh[tid] += v;
        __syncthreads();
    }
    int run = sh[tid] - s;
    for (int i = 0; i < SCAN_C; i++) {
        int idx = base + i;
        if (idx < NN) {
            off[idx] = run;
            cur[idx] = run;
            run += cnt[idx];
        }
    }
}

__global__ void fill_kernel(const int* __restrict__ recv,
                            const int* __restrict__ send) {
    int e = blockIdx.x * blockDim.x + threadIdx.x;
    if (e < NE) {
        int p = atomicAdd(&g_cur_in[recv[e]], 1);
        g_bin_in[p] = e;
        int q = atomicAdd(&g_cur_out[send[e]], 1);
        g_bin_out[q] = e;
    }
}

// ---------------------------------------------------------------------------
// Gather (verbatim R13)
// ---------------------------------------------------------------------------
__global__ void __launch_bounds__(256)
gather_kernel(const float* __restrict__ ef) {
    const int warp = threadIdx.x >> 5;
    const int lane = threadIdx.x & 31;
    const int node = blockIdx.x * 8 + warp;
    if (node >= NN) return;
    const int* off; const int* cnt; const int* bin; float* agg;
    if (blockIdx.y == 0) { off = g_off_in;  cnt = g_cnt_in;  bin = g_bin_in;  agg = g_agg_in; }
    else                 { off = g_off_out; cnt = g_cnt_out; bin = g_bin_out; agg = g_agg_out; }

    const int start = __ldg(off + node);
    const int end   = start + __ldg(cnt + node);
    const float4* ef4 = (const float4*)ef;
    float4 acc = make_float4(0.f, 0.f, 0.f, 0.f);

    int j = start;
    for (; j + 4 <= end; j += 4) {
        int i0 = __ldg(bin + j), i1 = __ldg(bin + j + 1);
        int i2 = __ldg(bin + j + 2), i3 = __ldg(bin + j + 3);
        float4 v0 = __ldg(ef4 + (size_t)i0 * 32 + lane);
        float4 v1 = __ldg(ef4 + (size_t)i1 * 32 + lane);
        float4 v2 = __ldg(ef4 + (size_t)i2 * 32 + lane);
        float4 v3 = __ldg(ef4 + (size_t)i3 * 32 + lane);
        acc.x += (v0.x + v1.x) + (v2.x + v3.x);
        acc.y += (v0.y + v1.y) + (v2.y + v3.y);
        acc.z += (v0.z + v1.z) + (v2.z + v3.z);
        acc.w += (v0.w + v1.w) + (v2.w + v3.w);
    }
    for (; j < end; j++) {
        int i0 = __ldg(bin + j);
        float4 v = __ldg(ef4 + (size_t)i0 * 32 + lane);
        acc.x += v.x; acc.y += v.y; acc.z += v.z; acc.w += v.w;
    }
    ((float4*)(agg + (size_t)node * FD))[lane] = acc;
}

// ---------------------------------------------------------------------------
// globproj (verbatim R13)
// ---------------------------------------------------------------------------
__global__ void __launch_bounds__(256)
globproj_kernel(const float* __restrict__ gf,
                const float* __restrict__ Wg,
                const float* __restrict__ bias) {
    const int warp = threadIdx.x >> 5;
    const int lane = threadIdx.x & 31;
    const int idx = blockIdx.x * 8 + warp;
    if (idx >= NG * FD) return;
    const int g = idx >> 7, n = idx & 127;
    const float* gr = gf + (size_t)g * FD;
    const float* wr = Wg + (size_t)n * FD;
    float s = 0.f;
    #pragma unroll
    for (int q = 0; q < 4; q++)
        s += __ldg(gr + lane + q * 32) * __ldg(wr + lane + q * 32);
    #pragma unroll
    for (int o = 16; o > 0; o >>= 1) s += __shfl_xor_sync(0xFFFFFFFFu, s, o);
    if (lane == 0) g_gp[idx] = s + __ldg(bias + n);
}

// ---------------------------------------------------------------------------
// B -> fp16, layout [n][384]
// ---------------------------------------------------------------------------
__global__ void b_split_kernel(const float* __restrict__ Wn,
                               const float* __restrict__ Wi,
                               const float* __restrict__ Wo) {
    int idx = blockIdx.x * blockDim.x + threadIdx.x;
    if (idx >= FD * 3 * FD) return;
    int n = idx / (3 * FD);
    int k = idx % (3 * FD);
    int seg = k >> 7, kk = k & 127;
    const float* W = (seg == 0) ? Wn : (seg == 1) ? Wi : Wo;
    g_Bh[idx] = __float2half_rn(W[n * FD + kk]);
}

// ---------------------------------------------------------------------------
// GEMM: mma.sync m16n8k16 fp16 SINGLE-TERM (error ~2^-11, under 1e-3).
// Software-pipelined (R13 structure), double-buffered, 40KB SMEM.
// ---------------------------------------------------------------------------
#define KP 40
#define TILE_BYTES (128 * KP * 2)        // 10240
#define STAGE_BYTES (2 * TILE_BYTES)     // 20480 (A + B)
#define AH_OFF(s) ((s) * STAGE_BYTES)
#define BH_OFF(s) ((s) * STAGE_BYTES + TILE_BYTES)
#define GEMM_SMEM (2 * STAGE_BYTES)      // 40960

#define MMA_F16(acc, a0, a1, a2, a3, b0, b1)                                \
    asm volatile(                                                           \
        "mma.sync.aligned.m16n8k16.row.col.f32.f16.f16.f32 "                \
        "{%0,%1,%2,%3}, {%4,%5,%6,%7}, {%8,%9}, {%0,%1,%2,%3};"             \
        : "+f"(acc[0]), "+f"(acc[1]), "+f"(acc[2]), "+f"(acc[3])            \
        : "r"(a0), "r"(a1), "r"(a2), "r"(a3), "r"(b0), "r"(b1))

__global__ void __launch_bounds__(256, 2)
gemm_mma_kernel(const float* __restrict__ node,
                const int* __restrict__ gidx,
                float* __restrict__ out) {
    extern __shared__ __align__(16) char smem[];
    const uint32_t sb = smem_u32(smem);
    __half* const smh = (__half*)smem;

    const int tid    = threadIdx.x;
    const int wid    = tid >> 5;
    const int lane   = tid & 31;
    const int gid    = lane >> 2;
    const int t2     = (lane & 3) * 2;
    const int warp_m = (wid & 3) * 32;
    const int warp_n = (wid >> 2) * 64;
    const int m0     = blockIdx.x * 128;

    const int arow  = tid >> 1;
    const int ahalf = tid & 1;
    const int gm    = m0 + arow;

    float acc[16][4];
    #pragma unroll
    for (int i = 0; i < 16; i++)
        #pragma unroll
        for (int j = 0; j < 4; j++) acc[i][j] = 0.f;

    // B loader: 2 cp.asyncs per thread into stage st
    auto load_B = [&](int kb, int st) {
        const int kglob = (kb >> 2) * FD + (kb & 3) * 32;
        #pragma unroll
        for (int i = 0; i < 2; i++) {
            int c = tid * 2 + i;
            int row = c >> 2, sub = c & 3;
            uint32_t doff = (uint32_t)(row * (KP * 2) + sub * 16);
            const __half* sh = g_Bh + (size_t)row * (3 * FD) + kglob + sub * 8;
            asm volatile("cp.async.cg.shared.global [%0], [%1], 16;"
                         :: "r"(sb + BH_OFF(st) + doff), "l"(sh) : "memory");
        }
        asm volatile("cp.async.commit_group;" ::: "memory");
    };
    // A LDG into regs
    auto load_A = [&](int kb, float4* v) {
        const int seg  = kb >> 2;
        const int kloc = (kb & 3) * 32;
        const float* X = (seg == 0) ? node : (seg == 1) ? g_agg_in : g_agg_out;
        #pragma unroll
        for (int j = 0; j < 4; j++) {
            if (gm < NN)
                v[j] = *(const float4*)(X + (size_t)gm * FD + kloc + ahalf * 16 + j * 4);
            else
                v[j] = make_float4(0.f, 0.f, 0.f, 0.f);
        }
    };
    // convert fp32 -> fp16 + STS into stage st
    auto store_A = [&](const float4* v, int st) {
        uint32_t hw[8];
        #pragma unroll
        for (int j = 0; j < 4; j++) {
            hw[j * 2 + 0] = pack_f16(v[j].x, v[j].y);
            hw[j * 2 + 1] = pack_f16(v[j].z, v[j].w);
        }
        __half* ah = smh + (AH_OFF(st) >> 1) + arow * KP + ahalf * 16;
        *(uint4*)(ah)     = make_uint4(hw[0], hw[1], hw[2], hw[3]);
        *(uint4*)(ah + 8) = make_uint4(hw[4], hw[5], hw[6], hw[7]);
    };

    // ---- prologue: stage chunk 0 into stage 0 ----
    {
        float4 v[4];
        load_B(0, 0);
        load_A(0, v);
        store_A(v, 0);
        asm volatile("cp.async.wait_group 0;" ::: "memory");
        __syncthreads();
    }

    #pragma unroll 1
    for (int kb = 0; kb < 12; kb++) {
        const int s = kb & 1;
        float4 v[4];
        const bool have_next = (kb < 11);
        if (have_next) {
            load_A(kb + 1, v);         // LDG early (in flight during MMAs)
            load_B(kb + 1, s ^ 1);     // cp.async into other stage
        }

        // ---- compute chunk kb from stage s ----
        const __half* Ash = smh + (AH_OFF(s) >> 1);
        const __half* Bsh = smh + (BH_OFF(s) >> 1);
        #pragma unroll
        for (int ks = 0; ks < 2; ks++) {
            const int kofs = ks * 16 + t2;
            uint32_t ah[2][4];
            #pragma unroll
            for (int ma = 0; ma < 2; ma++) {
                const int r = warp_m + ma * 16 + gid;
                ah[ma][0] = *(const uint32_t*)&Ash[r * KP + kofs];
                ah[ma][1] = *(const uint32_t*)&Ash[(r + 8) * KP + kofs];
                ah[ma][2] = *(const uint32_t*)&Ash[r * KP + kofs + 8];
                ah[ma][3] = *(const uint32_t*)&Ash[(r + 8) * KP + kofs + 8];
            }
            #pragma unroll
            for (int na = 0; na < 8; na++) {
                const int bn = warp_n + na * 8 + gid;
                uint32_t b0 = *(const uint32_t*)&Bsh[bn * KP + kofs];
                uint32_t b1 = *(const uint32_t*)&Bsh[bn * KP + kofs + 8];
                #pragma unroll
                for (int ma = 0; ma < 2; ma++) {
                    MMA_F16(acc[ma * 8 + na],
                            ah[ma][0], ah[ma][1], ah[ma][2], ah[ma][3], b0, b1);
                }
            }
        }

        if (have_next) {
            store_A(v, s ^ 1);                               // STS late
            asm volatile("cp.async.wait_group 0;" ::: "memory");
        }
        __syncthreads();
    }

    // ---- epilogue (verbatim R13) ----
    #pragma unroll
    for (int ma = 0; ma < 2; ma++) {
        const int mr0 = m0 + warp_m + ma * 16 + gid;
        const int mr1 = mr0 + 8;
        const int g0 = (mr0 < NN) ? __ldg(gidx + mr0) : 0;
        const int g1 = (mr1 < NN) ? __ldg(gidx + mr1) : 0;
        #pragma unroll
        for (int na = 0; na < 8; na++) {
            const int n = warp_n + na * 8 + t2;
            const float* a = acc[ma * 8 + na];
            if (mr0 < NN) {
                float2 b = *(const float2*)(g_gp + (size_t)g0 * FD + n);
                *(float2*)(out + (size_t)mr0 * FD + n) =
                    make_float2(a[0] + b.x, a[1] + b.y);
            }
            if (mr1 < NN) {
                float2 b = *(const float2*)(g_gp + (size_t)g1 * FD + n);
                *(float2*)(out + (size_t)mr1 * FD + n) =
                    make_float2(a[2] + b.x, a[3] + b.y);
            }
        }
    }
}

// ---------------------------------------------------------------------------
extern "C" void kernel_launch(void* const* d_in, const int* in_sizes, int n_in,
                              void* d_out, int out_size) {
    const float* node = (const float*)d_in[0];
    const float* edge = (const float*)d_in[1];
    const float* glob = (const float*)d_in[2];
    const float* Wn   = (const float*)d_in[3];
    const float* Wi   = (const float*)d_in[4];
    const float* Wo   = (const float*)d_in[5];
    const float* Wg   = (const float*)d_in[6];
    const float* bias = (const float*)d_in[7];
    const int* recv   = (const int*)d_in[8];
    const int* send   = (const int*)d_in[9];
    const int* gidx   = (const int*)d_in[10];
    float* out        = (float*)d_out;

    cudaFuncSetAttribute(gemm_mma_kernel,
                         cudaFuncAttributeMaxDynamicSharedMemorySize, GEMM_SMEM);

    // CSR build (R13)
    init_counts_kernel<<<(NN + 255) / 256, 256>>>();
    hist_kernel<<<(NE + 255) / 256, 256>>>(recv, send);
    scan_kernel<<<2, 1024>>>();
    fill_kernel<<<(NE + 255) / 256, 256>>>(recv, send);
    // aggregate via gather (R13)
    dim3 ggrid((NN + 7) / 8, 2);
    gather_kernel<<<ggrid, 256>>>(edge);
    // small preps
    b_split_kernel<<<(FD * 3 * FD + 255) / 256, 256>>>(Wn, Wi, Wo);
    globproj_kernel<<<(NG * FD + 7) / 8, 256>>>(glob, Wg, bias);
    // fused projection GEMM — fp16 single-term, pipelined
    gemm_mma_kernel<<<(NN + 127) / 128, 256, GEMM_SMEM>>>(node, gidx, out);
}